// round 5
// baseline (speedup 1.0000x reference)
#include <cuda_runtime.h>
#include <math.h>

// EstimateAdj: out = diag(1/rowsum(A*B + I)) @ (A*B + I), N=8192.
// R5: persistent CTAs (grid = #SMs), cp.async double-buffered row staging.
//     Row r+1's A/B stream into smem while row r is reduced and stored,
//     so DRAM loads never pause; no wave transitions.

#define N 8192
#define N4 (N / 4)           // 2048 float4 per row
#define TPB 1024
#define V 2                  // float4 per thread per row (2048/1024)
#define NWARPS (TPB / 32)    // 32

#define BUF_F4 (2 * N4)      // A (2048) + B (2048) float4 per buffer = 64KB
#define DYN_SMEM (2 * BUF_F4 * sizeof(float4))  // 128KB

__device__ __forceinline__ void cp_async16(float4* smem_dst, const float4* gsrc) {
    unsigned s = (unsigned)__cvta_generic_to_shared(smem_dst);
    asm volatile("cp.async.cg.shared.global [%0], [%1], 16;" :: "r"(s), "l"(gsrc));
}

__global__ __launch_bounds__(TPB, 1)
void estimate_adj_kernel(const float4* __restrict__ A,
                         const float4* __restrict__ B,
                         float4* __restrict__ out) {
    extern __shared__ float4 smem[];          // [2][BUF_F4]
    __shared__ float warp_sums[2][NWARPS];

    const int tid = threadIdx.x;
    const int stride = gridDim.x;

    // Each thread stages (and later reads) only its own chunks: indices
    // tid and tid+TPB of A and of B -> no cross-thread smem hazards.
    auto issue = [&](int buf, int row) {
        const long base = (long)row * N4;
        float4* sA = smem + buf * BUF_F4;
        float4* sB = sA + N4;
        cp_async16(sA + tid,       A + base + tid);
        cp_async16(sA + tid + TPB, A + base + tid + TPB);
        cp_async16(sB + tid,       B + base + tid);
        cp_async16(sB + tid + TPB, B + base + tid + TPB);
        asm volatile("cp.async.commit_group;" ::: "memory");
    };

    const int row0 = blockIdx.x;
    if (row0 < N) issue(0, row0);

    int buf = 0;
    int parity = 0;
    for (int r = row0; r < N; r += stride) {
        const int next = r + stride;
        if (next < N) {
            issue(buf ^ 1, next);                               // prefetch
            asm volatile("cp.async.wait_group 1;" ::: "memory"); // current ready
        } else {
            asm volatile("cp.async.wait_group 0;" ::: "memory");
        }

        const float4* sA = smem + buf * BUF_F4;
        const float4* sB = sA + N4;

        float4 p[V];
        float sum = 0.0f;
        #pragma unroll
        for (int j = 0; j < V; j++) {
            float4 a = sA[tid + j * TPB];
            float4 b = sB[tid + j * TPB];
            float4 m;
            m.x = a.x * b.x; m.y = a.y * b.y;
            m.z = a.z * b.z; m.w = a.w * b.w;
            p[j] = m;
            sum += (m.x + m.y) + (m.z + m.w);
        }

        #pragma unroll
        for (int off = 16; off > 0; off >>= 1)
            sum += __shfl_xor_sync(0xFFFFFFFFu, sum, off);
        if ((tid & 31) == 0) warp_sums[parity][tid >> 5] = sum;
        __syncthreads();

        float total = 1.0f;   // identity contributes +1 to the rowsum
        #pragma unroll
        for (int w = 0; w < NWARPS; w++) total += warp_sums[parity][w];
        float rinv = 1.0f / total;
        if (isinf(rinv)) rinv = 0.0f;

        const long base = (long)r * N4;
        const int diag4 = r >> 2;
        #pragma unroll
        for (int j = 0; j < V; j++) {
            const int idx = tid + j * TPB;
            float4 m = p[j];
            m.x *= rinv; m.y *= rinv; m.z *= rinv; m.w *= rinv;
            if (idx == diag4) ((float*)&m)[r & 3] += rinv;
            out[base + idx] = m;
        }

        buf ^= 1;
        parity ^= 1;
    }
}

extern "C" void kernel_launch(void* const* d_in, const int* in_sizes, int n_in,
                              void* d_out, int out_size) {
    const float4* A = (const float4*)d_in[0];   // estimated_adj
    const float4* B = (const float4*)d_in[1];   // ori
    float4* out = (float4*)d_out;

    int nsm = 148;
    cudaDeviceGetAttribute(&nsm, cudaDevAttrMultiProcessorCount, 0);

    static bool attr_set = false;
    cudaFuncSetAttribute(estimate_adj_kernel,
                         cudaFuncAttributeMaxDynamicSharedMemorySize, DYN_SMEM);
    (void)attr_set;

    estimate_adj_kernel<<<nsm, TPB, DYN_SMEM>>>(A, B, out);
}

// round 6
// speedup vs baseline: 1.1094x; 1.1094x over previous
#include <cuda_runtime.h>
#include <math.h>

// EstimateAdj: out = diag(1/rowsum(A*B + I)) @ (A*B + I), N=8192.
// R6: best shape (1 row/CTA, 256 thr, 8x float4 in regs) +
//     ld.global.nc.L2::256B (256-byte L2 fetch granularity for denser DRAM
//     requests) + algebraic diagonal + single-barrier reduction.

#define N 8192
#define N4 (N / 4)            // 2048 float4 per row
#define TPB 256
#define V_PER_T (N4 / TPB)    // 8 float4 per thread
#define NWARPS (TPB / 32)     // 8

__device__ __forceinline__ float4 ldg256(const float4* p) {
    float4 v;
    asm volatile("ld.global.nc.L2::256B.v4.f32 {%0,%1,%2,%3}, [%4];"
                 : "=f"(v.x), "=f"(v.y), "=f"(v.z), "=f"(v.w) : "l"(p));
    return v;
}

__global__ __launch_bounds__(TPB, 4)
void estimate_adj_kernel(const float4* __restrict__ A,
                         const float4* __restrict__ B,
                         float4* __restrict__ out) {
    const int row = blockIdx.x;
    const long base = (long)row * N4;
    const int tid = threadIdx.x;

    float4 p[V_PER_T];
    float sum = 0.0f;

    // Branch-free front-batched loads with 256B L2 fetch hint.
    #pragma unroll
    for (int j = 0; j < V_PER_T; j++) {
        const int idx = tid + j * TPB;   // 0..2047, coalesced
        float4 a = ldg256(A + base + idx);
        float4 b = ldg256(B + base + idx);
        float4 m;
        m.x = a.x * b.x;
        m.y = a.y * b.y;
        m.z = a.z * b.z;
        m.w = a.w * b.w;
        p[j] = m;
        sum += (m.x + m.y) + (m.z + m.w);
    }

    // Warp reduction
    #pragma unroll
    for (int off = 16; off > 0; off >>= 1)
        sum += __shfl_xor_sync(0xFFFFFFFFu, sum, off);

    __shared__ float warp_sums[NWARPS];
    const int lane = tid & 31;
    const int wid = tid >> 5;
    if (lane == 0) warp_sums[wid] = sum;
    __syncthreads();

    // Every thread finishes the reduction (single barrier).
    // Identity contributes exactly +1 to every rowsum.
    float total = 1.0f;
    #pragma unroll
    for (int w = 0; w < NWARPS; w++) total += warp_sums[w];
    float rinv = 1.0f / total;
    if (isinf(rinv)) rinv = 0.0f;

    // Scale and store from registers; diagonal fixup: out[row][row] += rinv.
    const int diag4 = row >> 2;
    #pragma unroll
    for (int j = 0; j < V_PER_T; j++) {
        const int idx = tid + j * TPB;
        float4 m = p[j];
        m.x *= rinv; m.y *= rinv; m.z *= rinv; m.w *= rinv;
        if (idx == diag4) ((float*)&m)[row & 3] += rinv;
        out[base + idx] = m;
    }
}

extern "C" void kernel_launch(void* const* d_in, const int* in_sizes, int n_in,
                              void* d_out, int out_size) {
    const float4* A = (const float4*)d_in[0];   // estimated_adj
    const float4* B = (const float4*)d_in[1];   // ori
    float4* out = (float4*)d_out;
    estimate_adj_kernel<<<N, TPB>>>(A, B, out);
}